// round 9
// baseline (speedup 1.0000x reference)
#include <cuda_runtime.h>
#include <math.h>

#define NPTS   73728            // 8*96*96
#define NCODE  4096
#define YELEMS 294912           // 8*4*96*96
#define LOSS_OFF YELEMS
#define IDX_OFF  (YELEMS + 1)
#define MARGIN  2e-4f           // >= 2x worst-case single-pass tf32 error

typedef unsigned int u32;

// ---------------- device scratch (no allocations allowed) ----------------
__device__ float  g_zz16[NPTS * 16];    // folded 16-dim point vectors [p][16]
__device__ float  g_S[NPTS];            // per-point |zf|^2 (32-dim, ref order)
__device__ float  g_wh[NCODE * 16];     // folded codebook, tf32 hi part
__device__ float  g_wfold[NCODE * 16];  // folded codebook, full fp32
__device__ float  g_Wsq[NCODE];         // fp32 |w_j|^2 (ref order)
__device__ int    g_idx[NPTS];
__device__ double g_part[288 * 5];      // loss partial sums per block

// tf32 round: returns tf32 value's bit pattern in a b32 register
__device__ __forceinline__ u32 to_tf32(float x) {
    u32 r; asm("cvt.rna.tf32.f32 %0, %1;" : "=r"(r) : "f"(x)); return r;
}

// m16n8k8 tf32 MMA, fp32 accumulate (legacy tensor path, valid on sm_100)
__device__ __forceinline__ void mma8(float c[4], u32 a0, u32 a1, u32 a2, u32 a3,
                                     u32 b0, u32 b1) {
    asm volatile(
        "mma.sync.aligned.m16n8k8.row.col.f32.tf32.tf32.f32 "
        "{%0,%1,%2,%3}, {%4,%5,%6,%7}, {%8,%9}, {%0,%1,%2,%3};"
        : "+f"(c[0]), "+f"(c[1]), "+f"(c[2]), "+f"(c[3])
        : "r"(a0), "r"(a1), "r"(a2), "r"(a3), "r"(b0), "r"(b1));
}

// exact fp32 distance (same fma order as the validated SIMT kernel)
__device__ float exact_d(int p, const float* __restrict__ bf_row,
                         float S, float Wv) {
    const float4* ap = (const float4*)&g_zz16[p * 16];
    float4 a0 = ap[0], a1 = ap[1], a2 = ap[2], a3 = ap[3];
    float M = 0.f;
    M = __fmaf_rn(a0.x, bf_row[0],  M); M = __fmaf_rn(a0.y, bf_row[1],  M);
    M = __fmaf_rn(a0.z, bf_row[2],  M); M = __fmaf_rn(a0.w, bf_row[3],  M);
    M = __fmaf_rn(a1.x, bf_row[4],  M); M = __fmaf_rn(a1.y, bf_row[5],  M);
    M = __fmaf_rn(a1.z, bf_row[6],  M); M = __fmaf_rn(a1.w, bf_row[7],  M);
    M = __fmaf_rn(a2.x, bf_row[8],  M); M = __fmaf_rn(a2.y, bf_row[9],  M);
    M = __fmaf_rn(a2.z, bf_row[10], M); M = __fmaf_rn(a2.w, bf_row[11], M);
    M = __fmaf_rn(a3.x, bf_row[12], M); M = __fmaf_rn(a3.y, bf_row[13], M);
    M = __fmaf_rn(a3.z, bf_row[14], M); M = __fmaf_rn(a3.w, bf_row[15], M);
    return __fmaf_rn(-2.f, M, __fadd_rn(S, Wv));
}

// =====================================================================
// K1: trilinear 2x upsample -> folded 16-dim vectors + S (ref rounding).
// =====================================================================
__global__ __launch_bounds__(256) void k_prep(const float* __restrict__ z) {
    int i = blockIdx.x * 256 + threadIdx.x;
    if (i >= NPTS) return;
    int n  = i % 96;
    int m  = (i / 96) % 96;
    int bb = i / (96 * 96);

    float vals[16];
    #pragma unroll
    for (int c = 0; c < 4; c++) {
        const float* zc = z + ((bb * 4 + c) * 9216);
        float A0[3], A1[3];
        #pragma unroll
        for (int dc = 0; dc < 3; dc++) {
            int col = n - 1 + dc;
            if (col < 0 || col > 95) { A0[dc] = 0.f; A1[dc] = 0.f; continue; }
            float zm = zc[m * 96 + col];
            float a0, a1;
            if (m == 0)  a0 = zm;
            else         a0 = __fadd_rn(__fmul_rn(0.25f, zc[(m - 1) * 96 + col]),
                                        __fmul_rn(0.75f, zm));
            if (m == 95) a1 = zm;
            else         a1 = __fadd_rn(__fmul_rn(0.75f, zm),
                                        __fmul_rn(0.25f, zc[(m + 1) * 96 + col]));
            A0[dc] = a0; A1[dc] = a1;
        }
        float v00 = (n == 0)  ? A0[1] : __fadd_rn(__fmul_rn(0.25f, A0[0]), __fmul_rn(0.75f, A0[1]));
        float v01 = (n == 95) ? A0[1] : __fadd_rn(__fmul_rn(0.75f, A0[1]), __fmul_rn(0.25f, A0[2]));
        float v10 = (n == 0)  ? A1[1] : __fadd_rn(__fmul_rn(0.25f, A1[0]), __fmul_rn(0.75f, A1[1]));
        float v11 = (n == 95) ? A1[1] : __fadd_rn(__fmul_rn(0.75f, A1[1]), __fmul_rn(0.25f, A1[2]));
        vals[c * 4 + 0] = v00; vals[c * 4 + 1] = v01;
        vals[c * 4 + 2] = v10; vals[c * 4 + 3] = v11;
    }

    float4* dst = (float4*)&g_zz16[i * 16];
    dst[0] = make_float4(vals[0],  vals[1],  vals[2],  vals[3]);
    dst[1] = make_float4(vals[4],  vals[5],  vals[6],  vals[7]);
    dst[2] = make_float4(vals[8],  vals[9],  vals[10], vals[11]);
    dst[3] = make_float4(vals[12], vals[13], vals[14], vals[15]);

    float S = 0.f;
    #pragma unroll
    for (int c = 0; c < 4; c++) {
        float sq[4];
        #pragma unroll
        for (int t = 0; t < 4; t++) sq[t] = __fmul_rn(vals[c * 4 + t], vals[c * 4 + t]);
        #pragma unroll
        for (int rep = 0; rep < 2; rep++) {
            S = __fadd_rn(S, sq[0]); S = __fadd_rn(S, sq[1]);
            S = __fadd_rn(S, sq[2]); S = __fadd_rn(S, sq[3]);
        }
    }
    g_S[i] = S;
}

// =====================================================================
// K2: fold codebook pairs -> fp32 + tf32 hi; |w_j|^2.
// =====================================================================
__global__ __launch_bounds__(256) void k_fold(const float* __restrict__ w) {
    int j = blockIdx.x * 256 + threadIdx.x;
    if (j >= NCODE) return;
    float wv[32];
    const float4* src = (const float4*)(w + j * 32);
    #pragma unroll
    for (int q = 0; q < 8; q++) {
        float4 v = src[q];
        wv[q * 4 + 0] = v.x; wv[q * 4 + 1] = v.y; wv[q * 4 + 2] = v.z; wv[q * 4 + 3] = v.w;
    }
    #pragma unroll
    for (int k = 0; k < 16; k++) {
        int e0 = ((k >> 2) << 3) + (k & 3);
        float wf = __fadd_rn(wv[e0], wv[e0 + 4]);
        g_wfold[j * 16 + k] = wf;
        g_wh[j * 16 + k] = __uint_as_float(to_tf32(wf));
    }
    float W = 0.f;
    #pragma unroll
    for (int e = 0; e < 32; e++) W = __fadd_rn(W, __fmul_rn(wv[e], wv[e]));
    g_Wsq[j] = W;
}

// =====================================================================
// K3: single-pass TF32 mma.sync + margin-triggered exact fp32 recheck.
//     CTA: 256 threads (8 warps) x 128 points; warp owns 16 points (m16).
//     Approx d via hi*hi only (2 MMAs/n8-tile). Any d_ap within MARGIN of
//     the thread-local running approx min gets an exact fp32 recompute;
//     final result is the exact lexicographic (d_ex, j) min => identical
//     to full-fp32 argmin (margin >= 2x worst-case tf32 error).
// =====================================================================
__global__ __launch_bounds__(256, 2) void k_argmin_mma() {
    __shared__ float Bh[256 * 20];   // tf32-hi rows, stride 20 (conflict-free)
    __shared__ float Bf[256 * 20];   // fp32 rows for exact recheck
    __shared__ float Ws[256];

    int tid  = threadIdx.x;
    int wid  = tid >> 5;
    int lane = tid & 31;
    int g = lane >> 2, t = lane & 3;
    int pbase = blockIdx.x * 128;
    int p0 = pbase + wid * 16 + g;
    int p1 = p0 + 8;

    // ---- A fragments: tf32 hi for both k-steps (built once) ----
    u32 ah[2][4];
    #pragma unroll
    for (int ks = 0; ks < 2; ks++) {
        ah[ks][0] = to_tf32(g_zz16[p0 * 16 + t + 8 * ks]);
        ah[ks][1] = to_tf32(g_zz16[p1 * 16 + t + 8 * ks]);
        ah[ks][2] = to_tf32(g_zz16[p0 * 16 + t + 4 + 8 * ks]);
        ah[ks][3] = to_tf32(g_zz16[p1 * 16 + t + 4 + 8 * ks]);
    }
    float S0 = g_S[p0], S1 = g_S[p1];

    float bd0 = __int_as_float(0x7f800000), bd1 = bd0;   // exact bests
    int   bj0 = 0, bj1 = 0;
    float map0 = __int_as_float(0x7f800000), map1 = map0; // approx running mins

    for (int nb = 0; nb < 16; nb++) {
        int nbase = nb * 256;
        __syncthreads();
        // stage B chunk (256 codes x 16k; tf32-hi + fp32) with row stride 20
        #pragma unroll
        for (int it = 0; it < 4; it++) {
            int f = it * 256 + tid;      // 1024 float4 per part
            int j = f >> 2, q = f & 3;
            *(float4*)&Bh[j * 20 + q * 4] = *(const float4*)&g_wh[(nbase + j) * 16 + q * 4];
            *(float4*)&Bf[j * 20 + q * 4] = *(const float4*)&g_wfold[(nbase + j) * 16 + q * 4];
        }
        Ws[tid] = g_Wsq[nbase + tid];
        __syncthreads();

        #pragma unroll 4
        for (int nt = 0; nt < 32; nt++) {
            const float* bhr = &Bh[(nt * 8 + g) * 20];
            u32 bh00 = __float_as_uint(bhr[t]);
            u32 bh01 = __float_as_uint(bhr[t + 4]);
            u32 bh10 = __float_as_uint(bhr[t + 8]);
            u32 bh11 = __float_as_uint(bhr[t + 12]);

            float c[4] = {0.f, 0.f, 0.f, 0.f};
            mma8(c, ah[0][0], ah[0][1], ah[0][2], ah[0][3], bh00, bh01);
            mma8(c, ah[1][0], ah[1][1], ah[1][2], ah[1][3], bh10, bh11);

            int nc0 = nt * 8 + 2 * t;
            float w0 = Ws[nc0], w1 = Ws[nc0 + 1];
            int j0 = nbase + nc0;
            float d00 = __fmaf_rn(-2.f, c[0], __fadd_rn(S0, w0));
            float d01 = __fmaf_rn(-2.f, c[1], __fadd_rn(S0, w1));
            float d10 = __fmaf_rn(-2.f, c[2], __fadd_rn(S1, w0));
            float d11 = __fmaf_rn(-2.f, c[3], __fadd_rn(S1, w1));

            // row p0 (ascending j within thread's columns)
            if (d00 < map0 + MARGIN) {
                float de = exact_d(p0, &Bf[nc0 * 20], S0, w0);
                if (de < bd0) { bd0 = de; bj0 = j0; }
            }
            map0 = fminf(map0, d00);
            if (d01 < map0 + MARGIN) {
                float de = exact_d(p0, &Bf[(nc0 + 1) * 20], S0, w1);
                if (de < bd0) { bd0 = de; bj0 = j0 + 1; }
            }
            map0 = fminf(map0, d01);
            // row p1
            if (d10 < map1 + MARGIN) {
                float de = exact_d(p1, &Bf[nc0 * 20], S1, w0);
                if (de < bd1) { bd1 = de; bj1 = j0; }
            }
            map1 = fminf(map1, d10);
            if (d11 < map1 + MARGIN) {
                float de = exact_d(p1, &Bf[(nc0 + 1) * 20], S1, w1);
                if (de < bd1) { bd1 = de; bj1 = j0 + 1; }
            }
            map1 = fminf(map1, d11);
        }
    }

    // lexicographic (d, j) reduce across the 4 lanes sharing each row
    #pragma unroll
    for (int off = 2; off > 0; off >>= 1) {
        float od = __shfl_down_sync(0xffffffffu, bd0, off, 4);
        int   oj = __shfl_down_sync(0xffffffffu, bj0, off, 4);
        if (od < bd0 || (od == bd0 && oj < bj0)) { bd0 = od; bj0 = oj; }
        od = __shfl_down_sync(0xffffffffu, bd1, off, 4);
        oj = __shfl_down_sync(0xffffffffu, bj1, off, 4);
        if (od < bd1 || (od == bd1 && oj < bj1)) { bd1 = od; bj1 = oj; }
    }
    if (t == 0) {
        g_idx[p0] = bj0;
        g_idx[p1] = bj1;
    }
}

// =====================================================================
// K4: gather codewords -> y, idx output, loss partial sums.
// =====================================================================
__global__ __launch_bounds__(256) void k_gather(const float* __restrict__ w,
                                                float* __restrict__ out,
                                                int out_size) {
    __shared__ double rbuf[8][5];
    int tid = threadIdx.x;
    int i = blockIdx.x * 256 + tid;

    int idx = g_idx[i];
    float cw[32];
    const float4* src = (const float4*)(w + idx * 32);
    #pragma unroll
    for (int q = 0; q < 8; q++) {
        float4 v = src[q];
        cw[q * 4 + 0] = v.x; cw[q * 4 + 1] = v.y; cw[q * 4 + 2] = v.z; cw[q * 4 + 3] = v.w;
    }
    float vv[16];
    const float4* vsrc = (const float4*)&g_zz16[i * 16];
    #pragma unroll
    for (int q = 0; q < 4; q++) {
        float4 v = vsrc[q];
        vv[q * 4 + 0] = v.x; vv[q * 4 + 1] = v.y; vv[q * 4 + 2] = v.z; vv[q * 4 + 3] = v.w;
    }

    int n = i % 96, m = (i / 96) % 96, bb = i / 9216;
    #pragma unroll
    for (int c = 0; c < 4; c++) {
        double s = 0.0;
        #pragma unroll
        for (int t = 0; t < 8; t++) s += (double)cw[c * 8 + t];
        int yoff = ((bb * 4 + c) * 9216) + m * 96 + n;
        if (yoff < out_size) out[yoff] = (float)(s * 0.125);
    }
    if (IDX_OFF + i < out_size) out[IDX_OFF + i] = (float)idx;

    double sq = 0, sz = 0, sq2 = 0, sz2 = 0, sx = 0;
    #pragma unroll
    for (int e = 0; e < 32; e++) {
        double q = (double)cw[e];
        double zv = (double)vv[(e >> 3) * 4 + (e & 3)];
        sq += q; sz += zv; sq2 += q * q; sz2 += zv * zv; sx += q * zv;
    }
    double vals[5] = {sq, sz, sq2, sz2, sx};
    int lane = tid & 31, warp = tid >> 5;
    #pragma unroll
    for (int s = 0; s < 5; s++) {
        double v = vals[s];
        #pragma unroll
        for (int off = 16; off > 0; off >>= 1)
            v += __shfl_down_sync(0xffffffffu, v, off);
        if (lane == 0) rbuf[warp][s] = v;
    }
    __syncthreads();
    if (warp == 0) {
        #pragma unroll
        for (int s = 0; s < 5; s++) {
            double v = (lane < 8) ? rbuf[lane][s] : 0.0;
            #pragma unroll
            for (int off = 4; off > 0; off >>= 1)
                v += __shfl_down_sync(0xffffffffu, v, off);
            if (lane == 0) g_part[blockIdx.x * 5 + s] = v;
        }
    }
}

// =====================================================================
// K5: final scalar — reg = 0.01*max column abs sum; loss assembly.
// =====================================================================
__global__ __launch_bounds__(1024) void k_final(const float* __restrict__ w,
                                                float* __restrict__ out,
                                                int out_size) {
    __shared__ double cp[32][33];
    __shared__ double ls[5];
    int t = threadIdx.x;
    int k = t & 31, g = t >> 5;
    double s = 0.0;
    int r0 = g * 128;
    #pragma unroll 4
    for (int r = 0; r < 128; r++) s += fabs((double)w[(r0 + r) * 32 + k]);
    cp[g][k] = s;
    __syncthreads();

    int warp = t >> 5, lane = t & 31;
    if (warp < 5) {
        double acc = 0.0;
        for (int b = lane; b < 288; b += 32) acc += g_part[b * 5 + warp];
        #pragma unroll
        for (int off = 16; off > 0; off >>= 1)
            acc += __shfl_down_sync(0xffffffffu, acc, off);
        if (lane == 0) ls[warp] = acc;
    }
    __syncthreads();

    if (t == 0) {
        double colmax = 0.0;
        for (int kk = 0; kk < 32; kk++) {
            double tot = 0.0;
            for (int gg = 0; gg < 32; gg++) tot += cp[gg][kk];
            if (tot > colmax) colmax = tot;
        }
        double nel = (double)NPTS * 32.0;
        double Sq = ls[0], Sz = ls[1], Sq2 = ls[2], Sz2 = ls[3], Sx = ls[4];
        double mse = (Sq2 - 2.0 * Sx + Sz2) / nel;
        double mq = Sq / nel, mz = Sz / nel;
        double cov = Sx - nel * mq * mz;
        double vq = Sq2 - nel * mq * mq;
        double vz = Sz2 - nel * mz * mz;
        double cost = cov / (sqrt(vq) * sqrt(vz));
        double loss = 1.25 * mse + (0.5 + 0.5 * cost) + 0.01 * colmax;
        if (LOSS_OFF < out_size) out[LOSS_OFF] = (float)loss;
    }
}

// =====================================================================
extern "C" void kernel_launch(void* const* d_in, const int* in_sizes, int n_in,
                              void* d_out, int out_size) {
    const float* z = (const float*)d_in[0];
    const float* w = (const float*)d_in[1];
    if (n_in >= 2 && in_sizes[0] == NCODE * 32 && in_sizes[1] == YELEMS) {
        const float* tmp = z; z = w; w = tmp;   // defensive input-order guard
    }
    float* out = (float*)d_out;

    k_prep      <<<288, 256>>>(z);
    k_fold      <<<16, 256>>>(w);
    k_argmin_mma<<<576, 256>>>();
    k_gather    <<<288, 256>>>(w, out, out_size);
    k_final     <<<1, 1024>>>(w, out, out_size);
}

// round 10
// speedup vs baseline: 2.3425x; 2.3425x over previous
#include <cuda_runtime.h>
#include <cuda_fp16.h>
#include <math.h>

#define NPTS   73728            // 8*96*96
#define NCODE  4096
#define YELEMS 294912           // 8*4*96*96
#define LOSS_OFF YELEMS
#define IDX_OFF  (YELEMS + 1)

#define SCALE_A 256.0f          // 2^8  (exact)
#define SCALE_B 16777216.0f     // 2^24 (exact)
#define DESCALE (-4.656612873077393e-10f)  // -2 / (2^8 * 2^24) = -2^-31, exact

typedef unsigned int u32;

// ---------------- device scratch (no allocations allowed) ----------------
__device__ float  g_zz16[NPTS * 16];    // folded 16-dim point vectors [p][16]
__device__ float  g_S[NPTS];            // per-point |zf|^2 (32-dim, ref order)
__device__ uint4  g_wp16[NCODE * 5];    // per code: 20 u32 = [8 hi fp16x2 | 8 lo fp16x2 | Wsq | pad3]
__device__ int    g_idx[NPTS];
__device__ double g_part[288 * 5];      // loss partial sums per block

// m16n8k16 fp16 MMA, fp32 accumulate (legacy tensor path, valid on sm_100)
__device__ __forceinline__ void mma16(float c[4], u32 a0, u32 a1, u32 a2, u32 a3,
                                      u32 b0, u32 b1) {
    asm volatile(
        "mma.sync.aligned.m16n8k16.row.col.f32.f16.f16.f32 "
        "{%0,%1,%2,%3}, {%4,%5,%6,%7}, {%8,%9}, {%0,%1,%2,%3};"
        : "+f"(c[0]), "+f"(c[1]), "+f"(c[2]), "+f"(c[3])
        : "r"(a0), "r"(a1), "r"(a2), "r"(a3), "r"(b0), "r"(b1));
}

__device__ __forceinline__ u32 pack2(__half x, __half y) {
    __half2 h = __halves2half2(x, y);
    return *(u32*)&h;
}

// =====================================================================
// K1: trilinear 2x upsample -> folded 16-dim vectors + S (ref rounding).
// =====================================================================
__global__ __launch_bounds__(256) void k_prep(const float* __restrict__ z) {
    int i = blockIdx.x * 256 + threadIdx.x;
    if (i >= NPTS) return;
    int n  = i % 96;
    int m  = (i / 96) % 96;
    int bb = i / (96 * 96);

    float vals[16];
    #pragma unroll
    for (int c = 0; c < 4; c++) {
        const float* zc = z + ((bb * 4 + c) * 9216);
        float A0[3], A1[3];
        #pragma unroll
        for (int dc = 0; dc < 3; dc++) {
            int col = n - 1 + dc;
            if (col < 0 || col > 95) { A0[dc] = 0.f; A1[dc] = 0.f; continue; }
            float zm = zc[m * 96 + col];
            float a0, a1;
            if (m == 0)  a0 = zm;
            else         a0 = __fadd_rn(__fmul_rn(0.25f, zc[(m - 1) * 96 + col]),
                                        __fmul_rn(0.75f, zm));
            if (m == 95) a1 = zm;
            else         a1 = __fadd_rn(__fmul_rn(0.75f, zm),
                                        __fmul_rn(0.25f, zc[(m + 1) * 96 + col]));
            A0[dc] = a0; A1[dc] = a1;
        }
        float v00 = (n == 0)  ? A0[1] : __fadd_rn(__fmul_rn(0.25f, A0[0]), __fmul_rn(0.75f, A0[1]));
        float v01 = (n == 95) ? A0[1] : __fadd_rn(__fmul_rn(0.75f, A0[1]), __fmul_rn(0.25f, A0[2]));
        float v10 = (n == 0)  ? A1[1] : __fadd_rn(__fmul_rn(0.25f, A1[0]), __fmul_rn(0.75f, A1[1]));
        float v11 = (n == 95) ? A1[1] : __fadd_rn(__fmul_rn(0.75f, A1[1]), __fmul_rn(0.25f, A1[2]));
        vals[c * 4 + 0] = v00; vals[c * 4 + 1] = v01;
        vals[c * 4 + 2] = v10; vals[c * 4 + 3] = v11;
    }

    float4* dst = (float4*)&g_zz16[i * 16];
    dst[0] = make_float4(vals[0],  vals[1],  vals[2],  vals[3]);
    dst[1] = make_float4(vals[4],  vals[5],  vals[6],  vals[7]);
    dst[2] = make_float4(vals[8],  vals[9],  vals[10], vals[11]);
    dst[3] = make_float4(vals[12], vals[13], vals[14], vals[15]);

    float S = 0.f;
    #pragma unroll
    for (int c = 0; c < 4; c++) {
        float sq[4];
        #pragma unroll
        for (int t = 0; t < 4; t++) sq[t] = __fmul_rn(vals[c * 4 + t], vals[c * 4 + t]);
        #pragma unroll
        for (int rep = 0; rep < 2; rep++) {
            S = __fadd_rn(S, sq[0]); S = __fadd_rn(S, sq[1]);
            S = __fadd_rn(S, sq[2]); S = __fadd_rn(S, sq[3]);
        }
    }
    g_S[i] = S;
}

// =====================================================================
// K2: fold codebook pairs -> scaled fp16 hi/lo rows + |w_j|^2.
//     Row layout (20 u32): [s]=hi pair (k=2s,2s+1), [8+s]=lo pair, [16]=Wsq.
// =====================================================================
__global__ __launch_bounds__(256) void k_fold(const float* __restrict__ w) {
    int j = blockIdx.x * 256 + threadIdx.x;
    if (j >= NCODE) return;
    float wv[32];
    const float4* src = (const float4*)(w + j * 32);
    #pragma unroll
    for (int q = 0; q < 8; q++) {
        float4 v = src[q];
        wv[q * 4 + 0] = v.x; wv[q * 4 + 1] = v.y; wv[q * 4 + 2] = v.z; wv[q * 4 + 3] = v.w;
    }
    float wf[16];
    #pragma unroll
    for (int k = 0; k < 16; k++) {
        int e0 = ((k >> 2) << 3) + (k & 3);
        wf[k] = __fmul_rn(__fadd_rn(wv[e0], wv[e0 + 4]), SCALE_B);  // pow2 scale, exact
    }
    u32 row[20];
    #pragma unroll
    for (int s = 0; s < 8; s++) {
        float x = wf[2 * s], y = wf[2 * s + 1];
        __half hx = __float2half_rn(x), hy = __float2half_rn(y);
        __half lx = __float2half_rn(__fadd_rn(x, -__half2float(hx)));
        __half ly = __float2half_rn(__fadd_rn(y, -__half2float(hy)));
        row[s]     = pack2(hx, hy);
        row[8 + s] = pack2(lx, ly);
    }
    float W = 0.f;
    #pragma unroll
    for (int e = 0; e < 32; e++) W = __fadd_rn(W, __fmul_rn(wv[e], wv[e]));
    row[16] = __float_as_uint(W);
    row[17] = 0u; row[18] = 0u; row[19] = 0u;

    uint4* dst = &g_wp16[j * 5];
    dst[0] = make_uint4(row[0],  row[1],  row[2],  row[3]);
    dst[1] = make_uint4(row[4],  row[5],  row[6],  row[7]);
    dst[2] = make_uint4(row[8],  row[9],  row[10], row[11]);
    dst[3] = make_uint4(row[12], row[13], row[14], row[15]);
    dst[4] = make_uint4(row[16], row[17], row[18], row[19]);
}

// =====================================================================
// K3: fp16 2-limb 3-product mma.sync GEMM + fused argmin.
//     CTA: 256 threads (8 warps) x 128 points; warp owns 16 points (m16).
//     Per n8-tile: 3 m16n8k16 MMAs (ah*bh, al*bh, ah*bl), fp32 accum.
//     d = fmaf(-2^-31, c, S+W); strict < with ascending j (jnp.argmin ties).
// =====================================================================
__global__ __launch_bounds__(256, 2) void k_argmin_mma() {
    __shared__ u32 Bp[256 * 20];    // interleaved rows, stride 20 (conflict-free)

    int tid  = threadIdx.x;
    int wid  = tid >> 5;
    int lane = tid & 31;
    int g = lane >> 2, t = lane & 3;
    int pbase = blockIdx.x * 128;
    int p0 = pbase + wid * 16 + g;
    int p1 = p0 + 8;

    // ---- A fragments: fp16 hi/lo, scaled by 2^8 (exact) ----
    u32 ah[4], al[4];
    {
        const float* z0 = &g_zz16[p0 * 16];
        const float* z1 = &g_zz16[p1 * 16];
        float a[4][2];
        a[0][0] = z0[2 * t] * SCALE_A;     a[0][1] = z0[2 * t + 1] * SCALE_A;
        a[1][0] = z1[2 * t] * SCALE_A;     a[1][1] = z1[2 * t + 1] * SCALE_A;
        a[2][0] = z0[2 * t + 8] * SCALE_A; a[2][1] = z0[2 * t + 9] * SCALE_A;
        a[3][0] = z1[2 * t + 8] * SCALE_A; a[3][1] = z1[2 * t + 9] * SCALE_A;
        #pragma unroll
        for (int q = 0; q < 4; q++) {
            __half hx = __float2half_rn(a[q][0]), hy = __float2half_rn(a[q][1]);
            __half lx = __float2half_rn(__fadd_rn(a[q][0], -__half2float(hx)));
            __half ly = __float2half_rn(__fadd_rn(a[q][1], -__half2float(hy)));
            ah[q] = pack2(hx, hy);
            al[q] = pack2(lx, ly);
        }
    }
    float S0 = g_S[p0], S1 = g_S[p1];

    float bd0 = __int_as_float(0x7f800000), bd1 = bd0;
    int   bj0 = 0, bj1 = 0;

    for (int nb = 0; nb < 16; nb++) {
        int nbase = nb * 256;
        __syncthreads();
        // stage B chunk: flat uint4 copy, 1280 uint4 (256 codes x 5)
        {
            uint4* s4 = (uint4*)Bp;
            const uint4* gsrc = &g_wp16[nbase * 5];
            #pragma unroll
            for (int it = 0; it < 5; it++)
                s4[it * 256 + tid] = gsrc[it * 256 + tid];
        }
        __syncthreads();

        #pragma unroll 4
        for (int nt = 0; nt < 32; nt++) {
            const u32* br = &Bp[(nt * 8 + g) * 20];
            u32 bh0 = br[t];
            u32 bh1 = br[t + 4];
            u32 bl0 = br[t + 8];
            u32 bl1 = br[t + 12];

            float c[4] = {0.f, 0.f, 0.f, 0.f};
            mma16(c, ah[0], ah[1], ah[2], ah[3], bh0, bh1);
            mma16(c, al[0], al[1], al[2], al[3], bh0, bh1);
            mma16(c, ah[0], ah[1], ah[2], ah[3], bl0, bl1);

            int nc0 = nt * 8 + 2 * t;
            float w0 = __uint_as_float(Bp[nc0 * 20 + 16]);
            float w1 = __uint_as_float(Bp[(nc0 + 1) * 20 + 16]);
            int j0 = nbase + nc0, j1 = j0 + 1;
            float d00 = __fmaf_rn(DESCALE, c[0], __fadd_rn(S0, w0));
            float d01 = __fmaf_rn(DESCALE, c[1], __fadd_rn(S0, w1));
            float d10 = __fmaf_rn(DESCALE, c[2], __fadd_rn(S1, w0));
            float d11 = __fmaf_rn(DESCALE, c[3], __fadd_rn(S1, w1));
            if (d00 < bd0) { bd0 = d00; bj0 = j0; }
            if (d01 < bd0) { bd0 = d01; bj0 = j1; }
            if (d10 < bd1) { bd1 = d10; bj1 = j0; }
            if (d11 < bd1) { bd1 = d11; bj1 = j1; }
        }
    }

    // lexicographic (d, j) reduce across the 4 lanes sharing each row
    #pragma unroll
    for (int off = 2; off > 0; off >>= 1) {
        float od = __shfl_down_sync(0xffffffffu, bd0, off, 4);
        int   oj = __shfl_down_sync(0xffffffffu, bj0, off, 4);
        if (od < bd0 || (od == bd0 && oj < bj0)) { bd0 = od; bj0 = oj; }
        od = __shfl_down_sync(0xffffffffu, bd1, off, 4);
        oj = __shfl_down_sync(0xffffffffu, bj1, off, 4);
        if (od < bd1 || (od == bd1 && oj < bj1)) { bd1 = od; bj1 = oj; }
    }
    if (t == 0) {
        g_idx[p0] = bj0;
        g_idx[p1] = bj1;
    }
}

// =====================================================================
// K4: gather codewords -> y, idx output, loss partial sums.
// =====================================================================
__global__ __launch_bounds__(256) void k_gather(const float* __restrict__ w,
                                                float* __restrict__ out,
                                                int out_size) {
    __shared__ double rbuf[8][5];
    int tid = threadIdx.x;
    int i = blockIdx.x * 256 + tid;

    int idx = g_idx[i];
    float cw[32];
    const float4* src = (const float4*)(w + idx * 32);
    #pragma unroll
    for (int q = 0; q < 8; q++) {
        float4 v = src[q];
        cw[q * 4 + 0] = v.x; cw[q * 4 + 1] = v.y; cw[q * 4 + 2] = v.z; cw[q * 4 + 3] = v.w;
    }
    float vv[16];
    const float4* vsrc = (const float4*)&g_zz16[i * 16];
    #pragma unroll
    for (int q = 0; q < 4; q++) {
        float4 v = vsrc[q];
        vv[q * 4 + 0] = v.x; vv[q * 4 + 1] = v.y; vv[q * 4 + 2] = v.z; vv[q * 4 + 3] = v.w;
    }

    int n = i % 96, m = (i / 96) % 96, bb = i / 9216;
    #pragma unroll
    for (int c = 0; c < 4; c++) {
        double s = 0.0;
        #pragma unroll
        for (int t = 0; t < 8; t++) s += (double)cw[c * 8 + t];
        int yoff = ((bb * 4 + c) * 9216) + m * 96 + n;
        if (yoff < out_size) out[yoff] = (float)(s * 0.125);
    }
    if (IDX_OFF + i < out_size) out[IDX_OFF + i] = (float)idx;

    double sq = 0, sz = 0, sq2 = 0, sz2 = 0, sx = 0;
    #pragma unroll
    for (int e = 0; e < 32; e++) {
        double q = (double)cw[e];
        double zv = (double)vv[(e >> 3) * 4 + (e & 3)];
        sq += q; sz += zv; sq2 += q * q; sz2 += zv * zv; sx += q * zv;
    }
    double vals[5] = {sq, sz, sq2, sz2, sx};
    int lane = tid & 31, warp = tid >> 5;
    #pragma unroll
    for (int s = 0; s < 5; s++) {
        double v = vals[s];
        #pragma unroll
        for (int off = 16; off > 0; off >>= 1)
            v += __shfl_down_sync(0xffffffffu, v, off);
        if (lane == 0) rbuf[warp][s] = v;
    }
    __syncthreads();
    if (warp == 0) {
        #pragma unroll
        for (int s = 0; s < 5; s++) {
            double v = (lane < 8) ? rbuf[lane][s] : 0.0;
            #pragma unroll
            for (int off = 4; off > 0; off >>= 1)
                v += __shfl_down_sync(0xffffffffu, v, off);
            if (lane == 0) g_part[blockIdx.x * 5 + s] = v;
        }
    }
}

// =====================================================================
// K5: final scalar — reg = 0.01*max column abs sum; loss assembly.
// =====================================================================
__global__ __launch_bounds__(1024) void k_final(const float* __restrict__ w,
                                                float* __restrict__ out,
                                                int out_size) {
    __shared__ double cp[32][33];
    __shared__ double ls[5];
    int t = threadIdx.x;
    int k = t & 31, g = t >> 5;
    double s = 0.0;
    int r0 = g * 128;
    #pragma unroll 4
    for (int r = 0; r < 128; r++) s += fabs((double)w[(r0 + r) * 32 + k]);
    cp[g][k] = s;
    __syncthreads();

    int warp = t >> 5, lane = t & 31;
    if (warp < 5) {
        double acc = 0.0;
        for (int b = lane; b < 288; b += 32) acc += g_part[b * 5 + warp];
        #pragma unroll
        for (int off = 16; off > 0; off >>= 1)
            acc += __shfl_down_sync(0xffffffffu, acc, off);
        if (lane == 0) ls[warp] = acc;
    }
    __syncthreads();

    if (t == 0) {
        double colmax = 0.0;
        for (int kk = 0; kk < 32; kk++) {
            double tot = 0.0;
            for (int gg = 0; gg < 32; gg++) tot += cp[gg][kk];
            if (tot > colmax) colmax = tot;
        }
        double nel = (double)NPTS * 32.0;
        double Sq = ls[0], Sz = ls[1], Sq2 = ls[2], Sz2 = ls[3], Sx = ls[4];
        double mse = (Sq2 - 2.0 * Sx + Sz2) / nel;
        double mq = Sq / nel, mz = Sz / nel;
        double cov = Sx - nel * mq * mz;
        double vq = Sq2 - nel * mq * mq;
        double vz = Sz2 - nel * mz * mz;
        double cost = cov / (sqrt(vq) * sqrt(vz));
        double loss = 1.25 * mse + (0.5 + 0.5 * cost) + 0.01 * colmax;
        if (LOSS_OFF < out_size) out[LOSS_OFF] = (float)loss;
    }
}

// =====================================================================
extern "C" void kernel_launch(void* const* d_in, const int* in_sizes, int n_in,
                              void* d_out, int out_size) {
    const float* z = (const float*)d_in[0];
    const float* w = (const float*)d_in[1];
    if (n_in >= 2 && in_sizes[0] == NCODE * 32 && in_sizes[1] == YELEMS) {
        const float* tmp = z; z = w; w = tmp;   // defensive input-order guard
    }
    float* out = (float*)d_out;

    k_prep      <<<288, 256>>>(z);
    k_fold      <<<16, 256>>>(w);
    k_argmin_mma<<<576, 256>>>();
    k_gather    <<<288, 256>>>(w, out, out_size);
    k_final     <<<1, 1024>>>(w, out, out_size);
}